// round 9
// baseline (speedup 1.0000x reference)
#include <cuda_runtime.h>
#include <cstdint>

#define BB 4
#define NN 4096
#define CC 128
#define NROWS (BB*NN)       // 16384
#define NCHUNK 32
#define TOTCHUNK (BB*NCHUNK)
#define XS_STRIDE 132
#define BSTRIDE 132

typedef unsigned long long u64;
__device__ __forceinline__ u64 pack2(float x, float y) {
    u64 r; asm("mov.b64 %0, {%1, %2};" : "=l"(r) : "f"(x), "f"(y)); return r;
}
__device__ __forceinline__ void unpack2(u64 v, float& x, float& y) {
    asm("mov.b64 {%0, %1}, %2;" : "=f"(x), "=f"(y) : "l"(v));
}
__device__ __forceinline__ u64 ffma2(u64 a, u64 b, u64 c) {
    u64 d; asm("fma.rn.f32x2 %0, %1, %2, %3;" : "=l"(d) : "l"(a), "l"(b), "l"(c)); return d;
}

// ---- scratch (device globals) ----
__device__ float  g_Q [NROWS*CC];
__device__ float  g_K [NROWS*CC];
__device__ float  g_Kh[NROWS*CC];
__device__ float  g_qnorm[NROWS];
__device__ float  g_knorm[NROWS];
__device__ float  g_Gpart[(size_t)TOTCHUNK*CC*CC];   // partial G = K̂^T X_v
__device__ double g_spart[TOTCHUNK*CC];
__device__ float  g_G[BB*CC*CC];
__device__ float  g_Mfin[BB*CC*CC];                  // M = G W^T + s b^T
__device__ double g_s[BB*CC];
__device__ double g_t[BB*CC];
__device__ double g_beta[BB];
__device__ double g_den[NROWS];
__device__ int    g_flag[NROWS];
__device__ int    g_bcount[BB];
__device__ int    g_list[BB*256];
__device__ double g_bpart[BB*256*32];

// ============================================================
__global__ void dummy_kernel() {}

// ============================================================
// proj: Y = X @ W^T + b (fp32, ascending-k chain, f32x2).
// W staged transposed ONCE (84.5KB dyn smem -> occ 2 by resources).
// z==0: q (+qn).  z==1: k (+kn, +k̂).
// ============================================================
__global__ void __launch_bounds__(256) proj_kernel(
    const float* __restrict__ q_in, const float* __restrict__ k_in,
    const float* __restrict__ W, const float* __restrict__ bias)
{
    extern __shared__ float sm[];
    float* Ws = sm;                     // Ws[c][d] = W[d][c]
    float* Xs = sm + 128*XS_STRIDE;

    const int tid = threadIdx.x;
    const int tx  = tid & 15;
    const int ty  = tid >> 4;
    const int z   = blockIdx.y;
    const float* X = (z == 0) ? q_in : k_in;
    const int row0 = blockIdx.x * 128;

    for (int i = tid; i < CC*CC; i += 256) {
        int d = i >> 7, c = i & 127;
        Ws[c*XS_STRIDE + d] = W[i];
    }

    u64 acc2[8][4];
    #pragma unroll
    for (int i = 0; i < 8; i++)
        #pragma unroll
        for (int jp = 0; jp < 4; jp++) acc2[i][jp] = 0ULL;

    for (int c0 = 0; c0 < CC; c0 += 32) {
        __syncthreads();
        for (int t = tid; t < 128*8; t += 256) {
            int r = t >> 3, cg = t & 7;
            float4 v = *(const float4*)(X + (size_t)(row0 + r)*CC + c0 + cg*4);
            Xs[(cg*4+0)*XS_STRIDE + r] = v.x;
            Xs[(cg*4+1)*XS_STRIDE + r] = v.y;
            Xs[(cg*4+2)*XS_STRIDE + r] = v.z;
            Xs[(cg*4+3)*XS_STRIDE + r] = v.w;
        }
        __syncthreads();
        #pragma unroll 4
        for (int kk = 0; kk < 32; kk++) {
            float a[8];
            *(float4*)&a[0] = *(float4*)&Xs[kk*XS_STRIDE + ty*8];
            *(float4*)&a[4] = *(float4*)&Xs[kk*XS_STRIDE + ty*8 + 4];
            const ulonglong2 bv0 = *(ulonglong2*)&Ws[(c0+kk)*XS_STRIDE + tx*8];
            const ulonglong2 bv1 = *(ulonglong2*)&Ws[(c0+kk)*XS_STRIDE + tx*8 + 4];
            u64 b2[4] = {bv0.x, bv0.y, bv1.x, bv1.y};
            #pragma unroll
            for (int i = 0; i < 8; i++) {
                const u64 as = pack2(a[i], a[i]);
                #pragma unroll
                for (int jp = 0; jp < 4; jp++)
                    acc2[i][jp] = ffma2(as, b2[jp], acc2[i][jp]);
            }
        }
    }

    float acc[8][8];
    #pragma unroll
    for (int i = 0; i < 8; i++)
        #pragma unroll
        for (int jp = 0; jp < 4; jp++)
            unpack2(acc2[i][jp], acc[i][2*jp], acc[i][2*jp+1]);

    float bj[8];
    *(float4*)&bj[0] = *(const float4*)&bias[tx*8];
    *(float4*)&bj[4] = *(const float4*)&bias[tx*8 + 4];
    #pragma unroll
    for (int i = 0; i < 8; i++)
        #pragma unroll
        for (int j = 0; j < 8; j++) acc[i][j] += bj[j];

    float nrm[8];
    #pragma unroll
    for (int i = 0; i < 8; i++) {
        float sq = 0.f;
        #pragma unroll
        for (int j = 0; j < 8; j++) sq = fmaf(acc[i][j], acc[i][j], sq);
        #pragma unroll
        for (int off = 8; off; off >>= 1)
            sq += __shfl_xor_sync(0xffffffffu, sq, off, 16);
        nrm[i] = sqrtf(sq);
        if (tx == 0) {
            if (z == 0) g_qnorm[row0 + ty*8 + i] = nrm[i];
            else        g_knorm[row0 + ty*8 + i] = nrm[i];
        }
    }

    #pragma unroll
    for (int i = 0; i < 8; i++) {
        const size_t off = (size_t)(row0 + ty*8 + i)*CC + tx*8;
        if (z == 0) {
            *(float4*)(g_Q + off)     = *(float4*)&acc[i][0];
            *(float4*)(g_Q + off + 4) = *(float4*)&acc[i][4];
        } else {
            *(float4*)(g_K + off)     = *(float4*)&acc[i][0];
            *(float4*)(g_K + off + 4) = *(float4*)&acc[i][4];
            const float inv = 1.f / nrm[i];
            float4 o0, o1;
            o0.x = acc[i][0]*inv; o0.y = acc[i][1]*inv;
            o0.z = acc[i][2]*inv; o0.w = acc[i][3]*inv;
            o1.x = acc[i][4]*inv; o1.y = acc[i][5]*inv;
            o1.z = acc[i][6]*inv; o1.w = acc[i][7]*inv;
            *(float4*)(g_Kh + off)     = o0;
            *(float4*)(g_Kh + off + 4) = o1;
        }
    }
}

// ============================================================
// kv: partial G = K̂^T X_v over 128-row chunks; partial s (fp64).
// ============================================================
__global__ void __launch_bounds__(256) kv_kernel(const float* __restrict__ v_in)
{
    extern __shared__ float sm[];
    float* Ks = sm;
    float* Vs = sm + CC*CC;
    const int tid = threadIdx.x;
    const int tx  = tid & 15;
    const int ty  = tid >> 4;
    const int blk = blockIdx.x;
    const size_t base = (size_t)blk * 128 * CC;

    const float4* K4 = (const float4*)(g_Kh + base);
    const float4* V4 = (const float4*)(v_in + base);
    for (int t = tid; t < 4096; t += 256) {
        ((float4*)Ks)[t] = K4[t];
        ((float4*)Vs)[t] = V4[t];
    }
    __syncthreads();

    u64 acc2[8][4];
    #pragma unroll
    for (int i = 0; i < 8; i++)
        #pragma unroll
        for (int jp = 0; jp < 4; jp++) acc2[i][jp] = 0ULL;

    #pragma unroll 4
    for (int n = 0; n < 128; n++) {
        float a[8];
        *(float4*)&a[0] = *(float4*)&Ks[n*CC + ty*8];
        *(float4*)&a[4] = *(float4*)&Ks[n*CC + ty*8 + 4];
        const ulonglong2 bv0 = *(ulonglong2*)&Vs[n*CC + tx*8];
        const ulonglong2 bv1 = *(ulonglong2*)&Vs[n*CC + tx*8 + 4];
        u64 b2[4] = {bv0.x, bv0.y, bv1.x, bv1.y};
        #pragma unroll
        for (int i = 0; i < 8; i++) {
            const u64 as = pack2(a[i], a[i]);
            #pragma unroll
            for (int jp = 0; jp < 4; jp++)
                acc2[i][jp] = ffma2(as, b2[jp], acc2[i][jp]);
        }
    }

    if (tid < 128) {
        double s0 = 0.0, s1 = 0.0, s2 = 0.0, s3 = 0.0;
        #pragma unroll 8
        for (int n = 0; n < 128; n += 4) {
            s0 += (double)Ks[(n+0)*CC + tid];
            s1 += (double)Ks[(n+1)*CC + tid];
            s2 += (double)Ks[(n+2)*CC + tid];
            s3 += (double)Ks[(n+3)*CC + tid];
        }
        g_spart[blk*CC + tid] = (s0 + s1) + (s2 + s3);
    }

    float* Gp = g_Gpart + (size_t)blk*CC*CC;
    #pragma unroll
    for (int i = 0; i < 8; i++) {
        float acc[8];
        #pragma unroll
        for (int jp = 0; jp < 4; jp++)
            unpack2(acc2[i][jp], acc[2*jp], acc[2*jp+1]);
        float* grow = Gp + (size_t)(ty*8 + i)*CC + tx*8;
        *(float4*)grow       = *(float4*)&acc[0];
        *(float4*)(grow + 4) = *(float4*)&acc[4];
    }
}

// ============================================================
__global__ void __launch_bounds__(256) reduce_kernel()
{
    const int g = blockIdx.x*256 + threadIdx.x;
    const int b  = g >> 12;
    const int e4 = g & 4095;
    float4 a = make_float4(0.f, 0.f, 0.f, 0.f);
    #pragma unroll
    for (int p = 0; p < NCHUNK; p++) {
        const float4 v = *(const float4*)&g_Gpart[(((size_t)((b << 5) + p)) << 14) + (e4 << 2)];
        a.x += v.x; a.y += v.y; a.z += v.z; a.w += v.w;
    }
    *(float4*)&g_G[(size_t)g << 2] = a;

    if (g < BB*CC) {
        const int b2 = g >> 7, i2 = g & 127;
        double s0 = 0.0, s1 = 0.0;
        #pragma unroll
        for (int p = 0; p < NCHUNK; p += 2) {
            s0 += g_spart[((b2 << 5) + p  )*CC + i2];
            s1 += g_spart[((b2 << 5) + p+1)*CC + i2];
        }
        g_s[g] = s0 + s1;
    }
}

// ============================================================
__global__ void __launch_bounds__(256) t_kernel(
    const float* __restrict__ W, const float* __restrict__ bias)
{
    const int wid = threadIdx.x >> 5;
    const int lane = threadIdx.x & 31;
    if (blockIdx.x < 64) {
        const int gidx = blockIdx.x*8 + wid;
        const int b = gidx >> 7, c = gidx & 127;
        double s = 0.0;
        #pragma unroll
        for (int u = 0; u < 4; u++) {
            const int d = lane + u*32;
            s += (double)W[d*CC + c] * g_s[b*CC + d];
        }
        #pragma unroll
        for (int off = 16; off; off >>= 1)
            s += __shfl_xor_sync(0xffffffffu, s, off);
        if (lane == 0) g_t[b*CC + c] = s;
    } else if (wid == 0) {
        const int b = blockIdx.x - 64;
        double be = 0.0;
        #pragma unroll
        for (int u = 0; u < 4; u++) {
            const int d = lane + u*32;
            be += (double)bias[d] * g_s[b*CC + d];
        }
        #pragma unroll
        for (int off = 16; off; off >>= 1)
            be += __shfl_xor_sync(0xffffffffu, be, off);
        if (lane == 0) g_beta[b] = be;
    }
}

// ============================================================
// mk: M[c][d] = sum_e G[c][e] W[d][e] + s_c * b_d.
// ============================================================
#define MK_SMEM ((128*XS_STRIDE + 128*36 + 128) * 4)
__global__ void __launch_bounds__(256, 1) mk_kernel(
    const float* __restrict__ W, const float* __restrict__ bias)
{
    extern __shared__ float sm[];
    float* Wt = sm;
    float* Gt = sm + 128*XS_STRIDE;
    float* sb = Gt + 128*36;

    const int tid = threadIdx.x;
    const int tx  = tid & 15;
    const int ty  = tid >> 4;
    const int b   = blockIdx.x >> 2;
    const int c0  = (blockIdx.x & 3) * 32;

    for (int i = tid; i < CC*CC; i += 256) {
        int d = i >> 7, e = i & 127;
        Wt[e*XS_STRIDE + d] = W[i];
    }
    for (int i = tid; i < 32*CC; i += 256) {
        int cl = i >> 7, e = i & 127;
        Gt[e*36 + cl] = g_G[(size_t)b*CC*CC + (size_t)(c0 + cl)*CC + e];
    }
    if (tid < 128) sb[tid] = bias[tid];
    __syncthreads();

    float acc[2][8] = {};
    #pragma unroll 4
    for (int e = 0; e < 128; e++) {
        const float a0 = Gt[e*36 + ty*2];
        const float a1 = Gt[e*36 + ty*2 + 1];
        float bb[8];
        *(float4*)&bb[0] = *(float4*)&Wt[e*XS_STRIDE + tx*8];
        *(float4*)&bb[4] = *(float4*)&Wt[e*XS_STRIDE + tx*8 + 4];
        #pragma unroll
        for (int j = 0; j < 8; j++) {
            acc[0][j] = fmaf(a0, bb[j], acc[0][j]);
            acc[1][j] = fmaf(a1, bb[j], acc[1][j]);
        }
    }

    #pragma unroll
    for (int i = 0; i < 2; i++) {
        const int c = c0 + ty*2 + i;
        const float sc = (float)g_s[b*CC + c];
        float4 o0, o1;
        o0.x = fmaf(sc, sb[tx*8+0], acc[i][0]);
        o0.y = fmaf(sc, sb[tx*8+1], acc[i][1]);
        o0.z = fmaf(sc, sb[tx*8+2], acc[i][2]);
        o0.w = fmaf(sc, sb[tx*8+3], acc[i][3]);
        o1.x = fmaf(sc, sb[tx*8+4], acc[i][4]);
        o1.y = fmaf(sc, sb[tx*8+5], acc[i][5]);
        o1.z = fmaf(sc, sb[tx*8+6], acc[i][6]);
        o1.w = fmaf(sc, sb[tx*8+7], acc[i][7]);
        float* mrow = g_Mfin + (size_t)b*CC*CC + (size_t)c*CC + tx*8;
        *(float4*)mrow       = o0;
        *(float4*)(mrow + 4) = o1;
    }
}

// ============================================================
__global__ void __launch_bounds__(256) den_kernel(const float* __restrict__ x)
{
    const int w = (blockIdx.x << 3) + (threadIdx.x >> 5);
    const int lane = threadIdx.x & 31;
    const int b = w >> 12;
    const float* xr = x + (size_t)w*CC;
    const double* t = g_t + b*CC;
    double s = 0.0;
    #pragma unroll
    for (int u = 0; u < 4; u++)
        s += (double)xr[lane + u*32] * t[lane + u*32];
    #pragma unroll
    for (int off = 16; off; off >>= 1)
        s += __shfl_xor_sync(0xffffffffu, s, off);
    if (lane == 0) {
        const double qn = (double)g_qnorm[w];
        const double num = s + g_beta[b];
        g_den[w] = num + 1e-8 * qn;
        g_flag[w] = (fabs(num / qn) < 2.0) ? 1 : 0;
    }
}

// ============================================================
__global__ void __launch_bounds__(256) compact_kernel()
{
    __shared__ int cnt[256];
    __shared__ int offs[256];
    const int t = threadIdx.x;
    for (int b = 0; b < BB; b++) {
        const int base = b*NN + t*(NN/256);
        int c = 0;
        #pragma unroll
        for (int i = 0; i < NN/256; i++) c += g_flag[base + i];
        cnt[t] = c;
        __syncthreads();
        if (t == 0) {
            int run = 0;
            for (int u = 0; u < 256; u++) { offs[u] = run; run += cnt[u]; }
            g_bcount[b] = run < 256 ? run : 256;
        }
        __syncthreads();
        int o = offs[t];
        #pragma unroll
        for (int i = 0; i < NN/256; i++) {
            const int row = base + i;
            if (g_flag[row]) { if (o < 256) g_list[b*256 + o] = row; o++; }
        }
        __syncthreads();
    }
}

// ============================================================
__global__ void __launch_bounds__(256, 1) brute_kernel()
{
    extern __shared__ float sm[];
    float* Qs  = sm;
    float* Kst = sm + 128*BSTRIDE;
    __shared__ float qn_s[128], kn_s[128];

    const int chunk = blockIdx.x;
    const int b     = blockIdx.y;
    const int tile  = blockIdx.z;
    int cnt = g_bcount[b] - tile*128;
    if (cnt <= 0) return;
    if (cnt > 128) cnt = 128;

    const int tid = threadIdx.x;
    const int tx  = tid & 15;
    const int ty  = tid >> 4;
    const int wid = tid >> 5;
    const int lane = tid & 31;
    const int key0 = b*NN + chunk*128;

    for (int t = tid; t < 128*BSTRIDE; t += 256) Qs[t] = 0.f;
    __syncthreads();

    for (int r = wid; r < cnt; r += 8) {
        const int row = g_list[b*256 + tile*128 + r];
        const float* qr = g_Q + (size_t)row*CC;
        #pragma unroll
        for (int u = 0; u < 4; u++) {
            const int c = lane + u*32;
            Qs[c*BSTRIDE + r] = qr[c];
        }
        if (lane == 0) qn_s[r] = g_qnorm[row];
    }
    for (int r = cnt + tid; r < 128; r += 256) qn_s[r] = 1.f;

    for (int r = wid; r < 128; r += 8) {
        const float* kr = g_K + (size_t)(key0 + r)*CC;
        #pragma unroll
        for (int u = 0; u < 4; u++) {
            const int c = lane + u*32;
            Kst[c*BSTRIDE + r] = kr[c];
        }
        if (lane == 0) kn_s[r] = g_knorm[key0 + r];
    }
    __syncthreads();

    u64 acc2[8][4];
    #pragma unroll
    for (int i = 0; i < 8; i++)
        #pragma unroll
        for (int jp = 0; jp < 4; jp++) acc2[i][jp] = 0ULL;

    #pragma unroll 4
    for (int c = 0; c < 128; c++) {
        float a[8];
        *(float4*)&a[0] = *(float4*)&Qs[c*BSTRIDE + ty*8];
        *(float4*)&a[4] = *(float4*)&Qs[c*BSTRIDE + ty*8 + 4];
        const ulonglong2 bv0 = *(ulonglong2*)&Kst[c*BSTRIDE + tx*8];
        const ulonglong2 bv1 = *(ulonglong2*)&Kst[c*BSTRIDE + tx*8 + 4];
        u64 b2[4] = {bv0.x, bv0.y, bv1.x, bv1.y};
        #pragma unroll
        for (int i = 0; i < 8; i++) {
            const u64 as = pack2(a[i], a[i]);
            #pragma unroll
            for (int jp = 0; jp < 4; jp++)
                acc2[i][jp] = ffma2(as, b2[jp], acc2[i][jp]);
        }
    }

    #pragma unroll
    for (int i = 0; i < 8; i++) {
        float acc[8];
        #pragma unroll
        for (int jp = 0; jp < 4; jp++)
            unpack2(acc2[i][jp], acc[2*jp], acc[2*jp+1]);
        const float qn = qn_s[ty*8 + i];
        double dsum = 0.0;
        #pragma unroll
        for (int j = 0; j < 8; j++) {
            const float d = qn * kn_s[tx*8 + j] + 1e-8f;
            dsum += (double)(acc[j] / d);
        }
        #pragma unroll
        for (int off = 8; off; off >>= 1)
            dsum += __shfl_xor_sync(0xffffffffu, dsum, off, 16);
        if (tx == 0)
            g_bpart[((size_t)(b*256 + tile*128 + ty*8 + i))*32 + chunk] = dsum;
    }
}

// ============================================================
__global__ void __launch_bounds__(256) combine_kernel()
{
    const int b = blockIdx.x;
    const int idx = threadIdx.x;
    if (idx >= g_bcount[b]) return;
    const int row = g_list[b*256 + idx];
    double s = 0.0;
    #pragma unroll
    for (int c = 0; c < 32; c++)
        s += g_bpart[((size_t)(b*256 + idx))*32 + c];
    g_den[row] = (double)g_qnorm[row] * (s + 1e-8);
}

// ============================================================
__global__ void __launch_bounds__(256, 2) out_kernel(float* __restrict__ out)
{
    extern __shared__ float sm[];
    float* Ms = sm;
    float* Xs = sm + CC*CC;

    const int tid = threadIdx.x;
    const int tx  = tid & 15;
    const int ty  = tid >> 4;
    const int b   = blockIdx.x >> 5;
    const int row0 = blockIdx.x * 128;

    const float4* M4 = (const float4*)(g_Mfin + (size_t)b*CC*CC);
    for (int t = tid; t < 4096; t += 256) ((float4*)Ms)[t] = M4[t];

    u64 acc2[8][4];
    #pragma unroll
    for (int i = 0; i < 8; i++)
        #pragma unroll
        for (int jp = 0; jp < 4; jp++) acc2[i][jp] = 0ULL;

    for (int c0 = 0; c0 < CC; c0 += 32) {
        __syncthreads();
        for (int t = tid; t < 128*8; t += 256) {
            int r = t >> 3, cg = t & 7;
            float4 v = *(const float4*)(g_Q + (size_t)(row0 + r)*CC + c0 + cg*4);
            Xs[(cg*4+0)*XS_STRIDE + r] = v.x;
            Xs[(cg*4+1)*XS_STRIDE + r] = v.y;
            Xs[(cg*4+2)*XS_STRIDE + r] = v.z;
            Xs[(cg*4+3)*XS_STRIDE + r] = v.w;
        }
        __syncthreads();
        #pragma unroll 4
        for (int kk = 0; kk < 32; kk++) {
            float a[8];
            *(float4*)&a[0] = *(float4*)&Xs[kk*XS_STRIDE + ty*8];
            *(float4*)&a[4] = *(float4*)&Xs[kk*XS_STRIDE + ty*8 + 4];
            const ulonglong2 bv0 = *(ulonglong2*)&Ms[(c0+kk)*CC + tx*8];
            const ulonglong2 bv1 = *(ulonglong2*)&Ms[(c0+kk)*CC + tx*8 + 4];
            u64 b2[4] = {bv0.x, bv0.y, bv1.x, bv1.y};
            #pragma unroll
            for (int i = 0; i < 8; i++) {
                const u64 as = pack2(a[i], a[i]);
                #pragma unroll
                for (int jp = 0; jp < 4; jp++)
                    acc2[i][jp] = ffma2(as, b2[jp], acc2[i][jp]);
            }
        }
    }

    #pragma unroll
    for (int i = 0; i < 8; i++) {
        float acc[8];
        #pragma unroll
        for (int jp = 0; jp < 4; jp++)
            unpack2(acc2[i][jp], acc[2*jp], acc[2*jp+1]);
        const double inv = 1.0 / g_den[row0 + ty*8 + i];
        float4 o0, o1;
        o0.x = (float)(acc[0]*inv); o0.y = (float)(acc[1]*inv);
        o0.z = (float)(acc[2]*inv); o0.w = (float)(acc[3]*inv);
        o1.x = (float)(acc[4]*inv); o1.y = (float)(acc[5]*inv);
        o1.z = (float)(acc[6]*inv); o1.w = (float)(acc[7]*inv);
        float* orow = out + (size_t)(row0 + ty*8 + i)*CC + tx*8;
        *(float4*)orow       = o0;
        *(float4*)(orow + 4) = o1;
    }
}

// ============================================================
extern "C" void kernel_launch(void* const* d_in, const int* in_sizes, int n_in,
                              void* d_out, int out_size)
{
    const float* q    = (const float*)d_in[0];
    const float* k    = (const float*)d_in[1];
    const float* v    = (const float*)d_in[2];
    const float* W    = (const float*)d_in[3];
    const float* bias = (const float*)d_in[4];
    float* out = (float*)d_out;

    const size_t sm1 = (size_t)(128 + 32) * XS_STRIDE * sizeof(float);   // 84.5KB
    const size_t sm2 = (size_t)2 * CC * CC * sizeof(float);
    const size_t sm3 = (size_t)(CC*CC + 32*XS_STRIDE) * sizeof(float);
    const size_t smB = (size_t)2 * 128 * BSTRIDE * sizeof(float);

    cudaFuncSetAttribute(proj_kernel,  cudaFuncAttributeMaxDynamicSharedMemorySize, (int)sm1);
    cudaFuncSetAttribute(kv_kernel,    cudaFuncAttributeMaxDynamicSharedMemorySize, (int)sm2);
    cudaFuncSetAttribute(mk_kernel,    cudaFuncAttributeMaxDynamicSharedMemorySize, MK_SMEM);
    cudaFuncSetAttribute(out_kernel,   cudaFuncAttributeMaxDynamicSharedMemorySize, (int)sm3);
    cudaFuncSetAttribute(brute_kernel, cudaFuncAttributeMaxDynamicSharedMemorySize, (int)smB);

    // 3 no-op pads so the ncu-profiled (4th) launch is proj_kernel
    dummy_kernel  <<<1, 32>>>();
    dummy_kernel  <<<1, 32>>>();
    dummy_kernel  <<<1, 32>>>();
    proj_kernel   <<<dim3(NROWS/128, 2), 256, sm1>>>(q, k, W, bias);
    kv_kernel     <<<TOTCHUNK, 256, sm2>>>(v);
    reduce_kernel <<<BB*CC*CC/(256*4), 256>>>();
    t_kernel      <<<68, 256>>>(W, bias);
    mk_kernel     <<<16, 256, MK_SMEM>>>(W, bias);
    den_kernel    <<<NROWS/8, 256>>>(q);
    compact_kernel<<<1, 256>>>();
    brute_kernel  <<<dim3(32, BB, 2), 256, smB>>>();
    combine_kernel<<<BB, 256>>>();
    out_kernel    <<<NROWS/128, 256, sm3>>>(out);
}

// round 10
// speedup vs baseline: 1.0506x; 1.0506x over previous
#include <cuda_runtime.h>
#include <cstdint>

#define BB 4
#define NN 4096
#define CC 128
#define NROWS (BB*NN)       // 16384
#define NCHUNK 32
#define TOTCHUNK (BB*NCHUNK)
#define XS_STRIDE 132
#define BSTRIDE 132

typedef unsigned long long u64;
__device__ __forceinline__ u64 pack2(float x, float y) {
    u64 r; asm("mov.b64 %0, {%1, %2};" : "=l"(r) : "f"(x), "f"(y)); return r;
}
__device__ __forceinline__ void unpack2(u64 v, float& x, float& y) {
    asm("mov.b64 {%0, %1}, %2;" : "=f"(x), "=f"(y) : "l"(v));
}
__device__ __forceinline__ u64 ffma2(u64 a, u64 b, u64 c) {
    u64 d; asm("fma.rn.f32x2 %0, %1, %2, %3;" : "=l"(d) : "l"(a), "l"(b), "l"(c)); return d;
}

// ---- scratch (device globals) ----
__device__ float  g_Q [NROWS*CC];
__device__ float  g_K [NROWS*CC];
__device__ float  g_Kh[NROWS*CC];
__device__ float  g_qnorm[NROWS];
__device__ float  g_knorm[NROWS];
__device__ float  g_Gpart[(size_t)TOTCHUNK*CC*CC];   // partial G = K̂^T X_v
__device__ double g_spart[TOTCHUNK*CC];
__device__ float  g_G[BB*CC*CC];
__device__ float  g_Mfin[BB*CC*CC];                  // M = G W^T + s b^T
__device__ double g_s[BB*CC];
__device__ double g_t[BB*CC];
__device__ double g_beta[BB];
__device__ double g_den[NROWS];
__device__ int    g_flag[NROWS];
__device__ int    g_bcount[BB];
__device__ int    g_list[BB*256];
__device__ double g_bpart[BB*256*32];

// ============================================================
__global__ void dummy_kernel() {}

// ============================================================
// proj: Y = X @ W^T + b (fp32, ascending-k chain, f32x2).
// Chunked W staging (r8 winner) + DOUBLE BUFFERING: one sync per
// chunk, next-chunk staging overlaps current-chunk FMA.
// z==0: q (+qn).  z==1: k (+kn, +k̂).
// ============================================================
#define PROJ_BUF (2*32*XS_STRIDE)                 // floats per buffer (Xs+Wc)
#define PROJ_SMEM (2*PROJ_BUF*4)                  // 67584 bytes

__global__ void __launch_bounds__(256, 2) proj_kernel(
    const float* __restrict__ q_in, const float* __restrict__ k_in,
    const float* __restrict__ W, const float* __restrict__ bias)
{
    extern __shared__ float sm[];
    // buffer p: Xs = sm + p*PROJ_BUF, Wc = sm + p*PROJ_BUF + 32*XS_STRIDE

    const int tid = threadIdx.x;
    const int tx  = tid & 15;
    const int ty  = tid >> 4;
    const int z   = blockIdx.y;
    const float* X = (z == 0) ? q_in : k_in;
    const int row0 = blockIdx.x * 128;

    u64 acc2[8][4];
    #pragma unroll
    for (int i = 0; i < 8; i++)
        #pragma unroll
        for (int jp = 0; jp < 4; jp++) acc2[i][jp] = 0ULL;

    // stage chunk 0 into buffer 0
    {
        float* Xs = sm;
        float* Wc = sm + 32*XS_STRIDE;
        for (int t = tid; t < 128*8; t += 256) {
            int r = t >> 3, cg = t & 7;
            float4 v = *(const float4*)(X + (size_t)(row0 + r)*CC + cg*4);
            Xs[(cg*4+0)*XS_STRIDE + r] = v.x;
            Xs[(cg*4+1)*XS_STRIDE + r] = v.y;
            Xs[(cg*4+2)*XS_STRIDE + r] = v.z;
            Xs[(cg*4+3)*XS_STRIDE + r] = v.w;
        }
        for (int t = tid; t < 128*8; t += 256) {
            int d = t >> 3, cg = t & 7;
            float4 w = *(const float4*)(W + (size_t)d*CC + cg*4);
            Wc[(cg*4+0)*XS_STRIDE + d] = w.x;
            Wc[(cg*4+1)*XS_STRIDE + d] = w.y;
            Wc[(cg*4+2)*XS_STRIDE + d] = w.z;
            Wc[(cg*4+3)*XS_STRIDE + d] = w.w;
        }
    }

    #pragma unroll
    for (int ci = 0; ci < 4; ci++) {
        __syncthreads();
        // stage next chunk into the other buffer (overlaps with compute)
        if (ci < 3) {
            const int c0n = (ci + 1) * 32;
            float* Xs = sm + ((ci + 1) & 1)*PROJ_BUF;
            float* Wc = Xs + 32*XS_STRIDE;
            for (int t = tid; t < 128*8; t += 256) {
                int r = t >> 3, cg = t & 7;
                float4 v = *(const float4*)(X + (size_t)(row0 + r)*CC + c0n + cg*4);
                Xs[(cg*4+0)*XS_STRIDE + r] = v.x;
                Xs[(cg*4+1)*XS_STRIDE + r] = v.y;
                Xs[(cg*4+2)*XS_STRIDE + r] = v.z;
                Xs[(cg*4+3)*XS_STRIDE + r] = v.w;
            }
            for (int t = tid; t < 128*8; t += 256) {
                int d = t >> 3, cg = t & 7;
                float4 w = *(const float4*)(W + (size_t)d*CC + c0n + cg*4);
                Wc[(cg*4+0)*XS_STRIDE + d] = w.x;
                Wc[(cg*4+1)*XS_STRIDE + d] = w.y;
                Wc[(cg*4+2)*XS_STRIDE + d] = w.z;
                Wc[(cg*4+3)*XS_STRIDE + d] = w.w;
            }
        }
        // compute current chunk
        float* Xs = sm + (ci & 1)*PROJ_BUF;
        float* Wc = Xs + 32*XS_STRIDE;
        #pragma unroll 4
        for (int kk = 0; kk < 32; kk++) {
            float a[8];
            *(float4*)&a[0] = *(float4*)&Xs[kk*XS_STRIDE + ty*8];
            *(float4*)&a[4] = *(float4*)&Xs[kk*XS_STRIDE + ty*8 + 4];
            const ulonglong2 bv0 = *(ulonglong2*)&Wc[kk*XS_STRIDE + tx*8];
            const ulonglong2 bv1 = *(ulonglong2*)&Wc[kk*XS_STRIDE + tx*8 + 4];
            u64 b2[4] = {bv0.x, bv0.y, bv1.x, bv1.y};
            #pragma unroll
            for (int i = 0; i < 8; i++) {
                const u64 as = pack2(a[i], a[i]);
                #pragma unroll
                for (int jp = 0; jp < 4; jp++)
                    acc2[i][jp] = ffma2(as, b2[jp], acc2[i][jp]);
            }
        }
    }

    float acc[8][8];
    #pragma unroll
    for (int i = 0; i < 8; i++)
        #pragma unroll
        for (int jp = 0; jp < 4; jp++)
            unpack2(acc2[i][jp], acc[i][2*jp], acc[i][2*jp+1]);

    float bj[8];
    *(float4*)&bj[0] = *(const float4*)&bias[tx*8];
    *(float4*)&bj[4] = *(const float4*)&bias[tx*8 + 4];
    #pragma unroll
    for (int i = 0; i < 8; i++)
        #pragma unroll
        for (int j = 0; j < 8; j++) acc[i][j] += bj[j];

    float nrm[8];
    #pragma unroll
    for (int i = 0; i < 8; i++) {
        float sq = 0.f;
        #pragma unroll
        for (int j = 0; j < 8; j++) sq = fmaf(acc[i][j], acc[i][j], sq);
        #pragma unroll
        for (int off = 8; off; off >>= 1)
            sq += __shfl_xor_sync(0xffffffffu, sq, off, 16);
        nrm[i] = sqrtf(sq);
        if (tx == 0) {
            if (z == 0) g_qnorm[row0 + ty*8 + i] = nrm[i];
            else        g_knorm[row0 + ty*8 + i] = nrm[i];
        }
    }

    #pragma unroll
    for (int i = 0; i < 8; i++) {
        const size_t off = (size_t)(row0 + ty*8 + i)*CC + tx*8;
        if (z == 0) {
            *(float4*)(g_Q + off)     = *(float4*)&acc[i][0];
            *(float4*)(g_Q + off + 4) = *(float4*)&acc[i][4];
        } else {
            *(float4*)(g_K + off)     = *(float4*)&acc[i][0];
            *(float4*)(g_K + off + 4) = *(float4*)&acc[i][4];
            const float inv = 1.f / nrm[i];
            float4 o0, o1;
            o0.x = acc[i][0]*inv; o0.y = acc[i][1]*inv;
            o0.z = acc[i][2]*inv; o0.w = acc[i][3]*inv;
            o1.x = acc[i][4]*inv; o1.y = acc[i][5]*inv;
            o1.z = acc[i][6]*inv; o1.w = acc[i][7]*inv;
            *(float4*)(g_Kh + off)     = o0;
            *(float4*)(g_Kh + off + 4) = o1;
        }
    }
}

// ============================================================
// kv: partial G = K̂^T X_v over 128-row chunks; partial s (fp64).
// ============================================================
__global__ void __launch_bounds__(256) kv_kernel(const float* __restrict__ v_in)
{
    extern __shared__ float sm[];
    float* Ks = sm;
    float* Vs = sm + CC*CC;
    const int tid = threadIdx.x;
    const int tx  = tid & 15;
    const int ty  = tid >> 4;
    const int blk = blockIdx.x;
    const size_t base = (size_t)blk * 128 * CC;

    const float4* K4 = (const float4*)(g_Kh + base);
    const float4* V4 = (const float4*)(v_in + base);
    for (int t = tid; t < 4096; t += 256) {
        ((float4*)Ks)[t] = K4[t];
        ((float4*)Vs)[t] = V4[t];
    }
    __syncthreads();

    u64 acc2[8][4];
    #pragma unroll
    for (int i = 0; i < 8; i++)
        #pragma unroll
        for (int jp = 0; jp < 4; jp++) acc2[i][jp] = 0ULL;

    #pragma unroll 4
    for (int n = 0; n < 128; n++) {
        float a[8];
        *(float4*)&a[0] = *(float4*)&Ks[n*CC + ty*8];
        *(float4*)&a[4] = *(float4*)&Ks[n*CC + ty*8 + 4];
        const ulonglong2 bv0 = *(ulonglong2*)&Vs[n*CC + tx*8];
        const ulonglong2 bv1 = *(ulonglong2*)&Vs[n*CC + tx*8 + 4];
        u64 b2[4] = {bv0.x, bv0.y, bv1.x, bv1.y};
        #pragma unroll
        for (int i = 0; i < 8; i++) {
            const u64 as = pack2(a[i], a[i]);
            #pragma unroll
            for (int jp = 0; jp < 4; jp++)
                acc2[i][jp] = ffma2(as, b2[jp], acc2[i][jp]);
        }
    }

    if (tid < 128) {
        double s0 = 0.0, s1 = 0.0, s2 = 0.0, s3 = 0.0;
        #pragma unroll 8
        for (int n = 0; n < 128; n += 4) {
            s0 += (double)Ks[(n+0)*CC + tid];
            s1 += (double)Ks[(n+1)*CC + tid];
            s2 += (double)Ks[(n+2)*CC + tid];
            s3 += (double)Ks[(n+3)*CC + tid];
        }
        g_spart[blk*CC + tid] = (s0 + s1) + (s2 + s3);
    }

    float* Gp = g_Gpart + (size_t)blk*CC*CC;
    #pragma unroll
    for (int i = 0; i < 8; i++) {
        float acc[8];
        #pragma unroll
        for (int jp = 0; jp < 4; jp++)
            unpack2(acc2[i][jp], acc[2*jp], acc[2*jp+1]);
        float* grow = Gp + (size_t)(ty*8 + i)*CC + tx*8;
        *(float4*)grow       = *(float4*)&acc[0];
        *(float4*)(grow + 4) = *(float4*)&acc[4];
    }
}

// ============================================================
__global__ void __launch_bounds__(256) reduce_kernel()
{
    const int g = blockIdx.x*256 + threadIdx.x;
    const int b  = g >> 12;
    const int e4 = g & 4095;
    float4 a = make_float4(0.f, 0.f, 0.f, 0.f);
    #pragma unroll
    for (int p = 0; p < NCHUNK; p++) {
        const float4 v = *(const float4*)&g_Gpart[(((size_t)((b << 5) + p)) << 14) + (e4 << 2)];
        a.x += v.x; a.y += v.y; a.z += v.z; a.w += v.w;
    }
    *(float4*)&g_G[(size_t)g << 2] = a;

    if (g < BB*CC) {
        const int b2 = g >> 7, i2 = g & 127;
        double s0 = 0.0, s1 = 0.0;
        #pragma unroll
        for (int p = 0; p < NCHUNK; p += 2) {
            s0 += g_spart[((b2 << 5) + p  )*CC + i2];
            s1 += g_spart[((b2 << 5) + p+1)*CC + i2];
        }
        g_s[g] = s0 + s1;
    }
}

// ============================================================
__global__ void __launch_bounds__(256) t_kernel(
    const float* __restrict__ W, const float* __restrict__ bias)
{
    const int wid = threadIdx.x >> 5;
    const int lane = threadIdx.x & 31;
    if (blockIdx.x < 64) {
        const int gidx = blockIdx.x*8 + wid;
        const int b = gidx >> 7, c = gidx & 127;
        double s = 0.0;
        #pragma unroll
        for (int u = 0; u < 4; u++) {
            const int d = lane + u*32;
            s += (double)W[d*CC + c] * g_s[b*CC + d];
        }
        #pragma unroll
        for (int off = 16; off; off >>= 1)
            s += __shfl_xor_sync(0xffffffffu, s, off);
        if (lane == 0) g_t[b*CC + c] = s;
    } else if (wid == 0) {
        const int b = blockIdx.x - 64;
        double be = 0.0;
        #pragma unroll
        for (int u = 0; u < 4; u++) {
            const int d = lane + u*32;
            be += (double)bias[d] * g_s[b*CC + d];
        }
        #pragma unroll
        for (int off = 16; off; off >>= 1)
            be += __shfl_xor_sync(0xffffffffu, be, off);
        if (lane == 0) g_beta[b] = be;
    }
}

// ============================================================
// mk: M[c][d] = sum_e G[c][e] W[d][e] + s_c * b_d.
// ============================================================
#define MK_SMEM ((128*XS_STRIDE + 128*36 + 128) * 4)
__global__ void __launch_bounds__(256, 1) mk_kernel(
    const float* __restrict__ W, const float* __restrict__ bias)
{
    extern __shared__ float sm[];
    float* Wt = sm;
    float* Gt = sm + 128*XS_STRIDE;
    float* sb = Gt + 128*36;

    const int tid = threadIdx.x;
    const int tx  = tid & 15;
    const int ty  = tid >> 4;
    const int b   = blockIdx.x >> 2;
    const int c0  = (blockIdx.x & 3) * 32;

    for (int i = tid; i < CC*CC; i += 256) {
        int d = i >> 7, e = i & 127;
        Wt[e*XS_STRIDE + d] = W[i];
    }
    for (int i = tid; i < 32*CC; i += 256) {
        int cl = i >> 7, e = i & 127;
        Gt[e*36 + cl] = g_G[(size_t)b*CC*CC + (size_t)(c0 + cl)*CC + e];
    }
    if (tid < 128) sb[tid] = bias[tid];
    __syncthreads();

    float acc[2][8] = {};
    #pragma unroll 4
    for (int e = 0; e < 128; e++) {
        const float a0 = Gt[e*36 + ty*2];
        const float a1 = Gt[e*36 + ty*2 + 1];
        float bb[8];
        *(float4*)&bb[0] = *(float4*)&Wt[e*XS_STRIDE + tx*8];
        *(float4*)&bb[4] = *(float4*)&Wt[e*XS_STRIDE + tx*8 + 4];
        #pragma unroll
        for (int j = 0; j < 8; j++) {
            acc[0][j] = fmaf(a0, bb[j], acc[0][j]);
            acc[1][j] = fmaf(a1, bb[j], acc[1][j]);
        }
    }

    #pragma unroll
    for (int i = 0; i < 2; i++) {
        const int c = c0 + ty*2 + i;
        const float sc = (float)g_s[b*CC + c];
        float4 o0, o1;
        o0.x = fmaf(sc, sb[tx*8+0], acc[i][0]);
        o0.y = fmaf(sc, sb[tx*8+1], acc[i][1]);
        o0.z = fmaf(sc, sb[tx*8+2], acc[i][2]);
        o0.w = fmaf(sc, sb[tx*8+3], acc[i][3]);
        o1.x = fmaf(sc, sb[tx*8+4], acc[i][4]);
        o1.y = fmaf(sc, sb[tx*8+5], acc[i][5]);
        o1.z = fmaf(sc, sb[tx*8+6], acc[i][6]);
        o1.w = fmaf(sc, sb[tx*8+7], acc[i][7]);
        float* mrow = g_Mfin + (size_t)b*CC*CC + (size_t)c*CC + tx*8;
        *(float4*)mrow       = o0;
        *(float4*)(mrow + 4) = o1;
    }
}

// ============================================================
__global__ void __launch_bounds__(256) den_kernel(const float* __restrict__ x)
{
    const int w = (blockIdx.x << 3) + (threadIdx.x >> 5);
    const int lane = threadIdx.x & 31;
    const int b = w >> 12;
    const float* xr = x + (size_t)w*CC;
    const double* t = g_t + b*CC;
    double s = 0.0;
    #pragma unroll
    for (int u = 0; u < 4; u++)
        s += (double)xr[lane + u*32] * t[lane + u*32];
    #pragma unroll
    for (int off = 16; off; off >>= 1)
        s += __shfl_xor_sync(0xffffffffu, s, off);
    if (lane == 0) {
        const double qn = (double)g_qnorm[w];
        const double num = s + g_beta[b];
        g_den[w] = num + 1e-8 * qn;
        g_flag[w] = (fabs(num / qn) < 2.0) ? 1 : 0;
    }
}

// ============================================================
__global__ void __launch_bounds__(256) compact_kernel()
{
    __shared__ int cnt[256];
    __shared__ int offs[256];
    const int t = threadIdx.x;
    for (int b = 0; b < BB; b++) {
        const int base = b*NN + t*(NN/256);
        int c = 0;
        #pragma unroll
        for (int i = 0; i < NN/256; i++) c += g_flag[base + i];
        cnt[t] = c;
        __syncthreads();
        if (t == 0) {
            int run = 0;
            for (int u = 0; u < 256; u++) { offs[u] = run; run += cnt[u]; }
            g_bcount[b] = run < 256 ? run : 256;
        }
        __syncthreads();
        int o = offs[t];
        #pragma unroll
        for (int i = 0; i < NN/256; i++) {
            const int row = base + i;
            if (g_flag[row]) { if (o < 256) g_list[b*256 + o] = row; o++; }
        }
        __syncthreads();
    }
}

// ============================================================
__global__ void __launch_bounds__(256, 1) brute_kernel()
{
    extern __shared__ float sm[];
    float* Qs  = sm;
    float* Kst = sm + 128*BSTRIDE;
    __shared__ float qn_s[128], kn_s[128];

    const int chunk = blockIdx.x;
    const int b     = blockIdx.y;
    const int tile  = blockIdx.z;
    int cnt = g_bcount[b] - tile*128;
    if (cnt <= 0) return;
    if (cnt > 128) cnt = 128;

    const int tid = threadIdx.x;
    const int tx  = tid & 15;
    const int ty  = tid >> 4;
    const int wid = tid >> 5;
    const int lane = tid & 31;
    const int key0 = b*NN + chunk*128;

    for (int t = tid; t < 128*BSTRIDE; t += 256) Qs[t] = 0.f;
    __syncthreads();

    for (int r = wid; r < cnt; r += 8) {
        const int row = g_list[b*256 + tile*128 + r];
        const float* qr = g_Q + (size_t)row*CC;
        #pragma unroll
        for (int u = 0; u < 4; u++) {
            const int c = lane + u*32;
            Qs[c*BSTRIDE + r] = qr[c];
        }
        if (lane == 0) qn_s[r] = g_qnorm[row];
    }
    for (int r = cnt + tid; r < 128; r += 256) qn_s[r] = 1.f;

    for (int r = wid; r < 128; r += 8) {
        const float* kr = g_K + (size_t)(key0 + r)*CC;
        #pragma unroll
        for (int u = 0; u < 4; u++) {
            const int c = lane + u*32;
            Kst[c*BSTRIDE + r] = kr[c];
        }
        if (lane == 0) kn_s[r] = g_knorm[key0 + r];
    }
    __syncthreads();

    u64 acc2[8][4];
    #pragma unroll
    for (int i = 0; i < 8; i++)
        #pragma unroll
        for (int jp = 0; jp < 4; jp++) acc2[i][jp] = 0ULL;

    #pragma unroll 4
    for (int c = 0; c < 128; c++) {
        float a[8];
        *(float4*)&a[0] = *(float4*)&Qs[c*BSTRIDE + ty*8];
        *(float4*)&a[4] = *(float4*)&Qs[c*BSTRIDE + ty*8 + 4];
        const ulonglong2 bv0 = *(ulonglong2*)&Kst[c*BSTRIDE + tx*8];
        const ulonglong2 bv1 = *(ulonglong2*)&Kst[c*BSTRIDE + tx*8 + 4];
        u64 b2[4] = {bv0.x, bv0.y, bv1.x, bv1.y};
        #pragma unroll
        for (int i = 0; i < 8; i++) {
            const u64 as = pack2(a[i], a[i]);
            #pragma unroll
            for (int jp = 0; jp < 4; jp++)
                acc2[i][jp] = ffma2(as, b2[jp], acc2[i][jp]);
        }
    }

    #pragma unroll
    for (int i = 0; i < 8; i++) {
        float acc[8];
        #pragma unroll
        for (int jp = 0; jp < 4; jp++)
            unpack2(acc2[i][jp], acc[2*jp], acc[2*jp+1]);
        const float qn = qn_s[ty*8 + i];
        double dsum = 0.0;
        #pragma unroll
        for (int j = 0; j < 8; j++) {
            const float d = qn * kn_s[tx*8 + j] + 1e-8f;
            dsum += (double)(acc[j] / d);
        }
        #pragma unroll
        for (int off = 8; off; off >>= 1)
            dsum += __shfl_xor_sync(0xffffffffu, dsum, off, 16);
        if (tx == 0)
            g_bpart[((size_t)(b*256 + tile*128 + ty*8 + i))*32 + chunk] = dsum;
    }
}

// ============================================================
__global__ void __launch_bounds__(256) combine_kernel()
{
    const int b = blockIdx.x;
    const int idx = threadIdx.x;
    if (idx >= g_bcount[b]) return;
    const int row = g_list[b*256 + idx];
    double s = 0.0;
    #pragma unroll
    for (int c = 0; c < 32; c++)
        s += g_bpart[((size_t)(b*256 + idx))*32 + c];
    g_den[row] = (double)g_qnorm[row] * (s + 1e-8);
}

// ============================================================
__global__ void __launch_bounds__(256, 2) out_kernel(float* __restrict__ out)
{
    extern __shared__ float sm[];
    float* Ms = sm;
    float* Xs = sm + CC*CC;

    const int tid = threadIdx.x;
    const int tx  = tid & 15;
    const int ty  = tid >> 4;
    const int b   = blockIdx.x >> 5;
    const int row0 = blockIdx.x * 128;

    const float4* M4 = (const float4*)(g_Mfin + (size_t)b*CC*CC);
    for (int t = tid; t < 4096; t += 256) ((float4*)Ms)[t] = M4[t];

    u64 acc2[8][4];
    #pragma unroll
    for (int i = 0; i < 8; i++)
        #pragma unroll
        for (int jp = 0; jp < 4; jp++) acc2[i][jp] = 0ULL;

    for (int c0 = 0; c0 < CC; c0 += 32) {
        __syncthreads();
        for (int t = tid; t < 128*8; t += 256) {
            int r = t >> 3, cg = t & 7;
            float4 v = *(const float4*)(g_Q + (size_t)(row0 + r)*CC + c0 + cg*4);
            Xs[(cg*4+0)*XS_STRIDE + r] = v.x;
            Xs[(cg*4+1)*XS_STRIDE + r] = v.y;
            Xs[(cg*4+2)*XS_STRIDE + r] = v.z;
            Xs[(cg*4+3)*XS_STRIDE + r] = v.w;
        }
        __syncthreads();
        #pragma unroll 4
        for (int kk = 0; kk < 32; kk++) {
            float a[8];
            *(float4*)&a[0] = *(float4*)&Xs[kk*XS_STRIDE + ty*8];
            *(float4*)&a[4] = *(float4*)&Xs[kk*XS_STRIDE + ty*8 + 4];
            const ulonglong2 bv0 = *(ulonglong2*)&Ms[(c0+kk)*CC + tx*8];
            const ulonglong2 bv1 = *(ulonglong2*)&Ms[(c0+kk)*CC + tx*8 + 4];
            u64 b2[4] = {bv0.x, bv0.y, bv1.x, bv1.y};
            #pragma unroll
            for (int i = 0; i < 8; i++) {
                const u64 as = pack2(a[i], a[i]);
                #pragma unroll
                for (int jp = 0; jp < 4; jp++)
                    acc2[i][jp] = ffma2(as, b2[jp], acc2[i][jp]);
            }
        }
    }

    #pragma unroll
    for (int i = 0; i < 8; i++) {
        float acc[8];
        #pragma unroll
        for (int jp = 0; jp < 4; jp++)
            unpack2(acc2[i][jp], acc[2*jp], acc[2*jp+1]);
        const double inv = 1.0 / g_den[row0 + ty*8 + i];
        float4 o0, o1;
        o0.x = (float)(acc[0]*inv); o0.y = (float)(acc[1]*inv);
        o0.z = (float)(acc[2]*inv); o0.w = (float)(acc[3]*inv);
        o1.x = (float)(acc[4]*inv); o1.y = (float)(acc[5]*inv);
        o1.z = (float)(acc[6]*inv); o1.w = (float)(acc[7]*inv);
        float* orow = out + (size_t)(row0 + ty*8 + i)*CC + tx*8;
        *(float4*)orow       = o0;
        *(float4*)(orow + 4) = o1;
    }
}

// ============================================================
extern "C" void kernel_launch(void* const* d_in, const int* in_sizes, int n_in,
                              void* d_out, int out_size)
{
    const float* q    = (const float*)d_in[0];
    const float* k    = (const float*)d_in[1];
    const float* v    = (const float*)d_in[2];
    const float* W    = (const float*)d_in[3];
    const float* bias = (const float*)d_in[4];
    float* out = (float*)d_out;

    const size_t sm2 = (size_t)2 * CC * CC * sizeof(float);
    const size_t sm3 = (size_t)(CC*CC + 32*XS_STRIDE) * sizeof(float);
    const size_t smB = (size_t)2 * 128 * BSTRIDE * sizeof(float);

    cudaFuncSetAttribute(proj_kernel,  cudaFuncAttributeMaxDynamicSharedMemorySize, PROJ_SMEM);
    cudaFuncSetAttribute(kv_kernel,    cudaFuncAttributeMaxDynamicSharedMemorySize, (int)sm2);
    cudaFuncSetAttribute(mk_kernel,    cudaFuncAttributeMaxDynamicSharedMemorySize, MK_SMEM);
    cudaFuncSetAttribute(out_kernel,   cudaFuncAttributeMaxDynamicSharedMemorySize, (int)sm3);
    cudaFuncSetAttribute(brute_kernel, cudaFuncAttributeMaxDynamicSharedMemorySize, (int)smB);

    // order: the 4th launch (ncu target) is kv_kernel this time
    proj_kernel   <<<dim3(NROWS/128, 2), 256, PROJ_SMEM>>>(q, k, W, bias);
    dummy_kernel  <<<1, 32>>>();
    dummy_kernel  <<<1, 32>>>();
    kv_kernel     <<<TOTCHUNK, 256, sm2>>>(v);
    reduce_kernel <<<BB*CC*CC/(256*4), 256>>>();
    t_kernel      <<<68, 256>>>(W, bias);
    mk_kernel     <<<16, 256, MK_SMEM>>>(W, bias);
    den_kernel    <<<NROWS/8, 256>>>(q);
    compact_kernel<<<1, 256>>>();
    brute_kernel  <<<dim3(32, BB, 2), 256, smB>>>();
    combine_kernel<<<BB, 256>>>();
    out_kernel    <<<NROWS/128, 256, sm3>>>(out);
}